// round 11
// baseline (speedup 1.0000x reference)
#include <cuda_runtime.h>
#include <cstdint>

// ============================================================================
// ForexLSTM: 2-layer LSTM (B=512, T=1024, H=65) + final linear.
//
// R9:
//  - recur_kernel: single barrier per step. Lane-quad gate ownership
//    (warp w = units 8w..8w+7, lane = unit*4 + gate). Own-gate activation,
//    8 full-mask idx-shfls to gather the quad's 4 activated gates, then a
//    REDUNDANT in-register cell update in all 4 lanes (bit-identical);
//    lane k==0 publishes h. No phase-2, no gates smem round-trip.
//  - pre_kernel / final_linear: unchanged from R8.
// ============================================================================

using u32 = unsigned int;
using ull = unsigned long long;

constexpr int B = 512, T = 1024, H = 65, G4 = 260;
constexpr int PTHR = 288, PGRID = 296;
constexpr int TILE = 8;                       // rows per pre tile
constexpr int NTILES = (B * T) / TILE;        // 65536
constexpr int RTHR = 288, RGRID = 256;        // 2 rows per CTA

__device__ float g_pre[(size_t)B * T * G4];   // 545 MB scratch
__device__ float g_h1 [(size_t)B * T * H];    // layer-0 output sequence
__device__ float g_hN [B * H];                // layer-1 last-step h

// ---------------- packed f32x2 helpers ----------------
__device__ __forceinline__ ull pack2(float x, float y) {
    ull r; asm("mov.b64 %0, {%1, %2};" : "=l"(r) : "f"(x), "f"(y)); return r;
}
__device__ __forceinline__ float2 unpack2(ull v) {
    float2 r; asm("mov.b64 {%0, %1}, %2;" : "=f"(r.x), "=f"(r.y) : "l"(v)); return r;
}
__device__ __forceinline__ void fma2(ull& d, ull a, ull b) {
    asm("fma.rn.f32x2 %0, %1, %2, %0;" : "+l"(d) : "l"(a), "l"(b));
}
__device__ __forceinline__ void lds128(ull& a, ull& b, u32 addr) {
    asm volatile("ld.shared.v2.u64 {%0, %1}, [%2];" : "=l"(a), "=l"(b) : "r"(addr));
}
__device__ __forceinline__ ull lds64(u32 addr) {
    ull a; asm volatile("ld.shared.u64 %0, [%1];" : "=l"(a) : "r"(addr)); return a;
}
__device__ __forceinline__ float fast_sigmoid(float v) {
    return __fdividef(1.0f, 1.0f + __expf(-v));
}
__device__ __forceinline__ float fast_tanh(float v) {
    return 1.0f - 2.0f * __fdividef(1.0f, __expf(2.0f * v) + 1.0f);
}

// ============================================================================
// pre[row, g] = (b_ih[g]+b_hh[g]) + sum_i xin[row,i] * w_ih[g,i]
// 8-row tiles, double-buffered; one __syncthreads per tile.  (unchanged)
// ============================================================================
__global__ void __launch_bounds__(PTHR, 2)
pre_kernel(const float* __restrict__ x_ext,
           const float* __restrict__ w_ih,
           const float* __restrict__ b_ih,
           const float* __restrict__ b_hh,
           int layer)
{
    const float* xin = (layer == 0) ? x_ext : g_h1;

    __shared__ __align__(16) float xs[2][TILE * 68];
    const int tid = threadIdx.x;
    const bool act = tid < G4;

    ull wih[33]; float bg = 0.f;
    if (act) {
        const float* wi = w_ih + tid * H;
#pragma unroll
        for (int j = 0; j < 32; j++)
            wih[j] = pack2(__ldg(wi + 2 * j), __ldg(wi + 2 * j + 1));
        wih[32] = pack2(__ldg(wi + 64), 0.f);
        bg = __ldg(b_ih + tid) + __ldg(b_hh + tid);
    }
    for (int k = tid; k < 2 * TILE * 68; k += PTHR) (&xs[0][0])[k] = 0.f;
    __syncthreads();

    const int f0 = tid, f1 = tid + 260;
    const int s0 = (f0 / 65) * 68 + (f0 % 65);
    const int s1 = (f1 / 65) * 68 + (f1 % 65);

    int gi = blockIdx.x;
    if (act) {
        const float* src = xin + (size_t)gi * (TILE * H);
        xs[0][s0] = __ldg(src + f0);
        xs[0][s1] = __ldg(src + f1);
    }
    __syncthreads();

    const u32 xb = (u32)__cvta_generic_to_shared(&xs[0][0]);
    int cur = 0;
    for (; gi < NTILES; gi += PGRID) {
        const int gn = gi + PGRID;
        float xn0 = 0.f, xn1 = 0.f;
        if (act && gn < NTILES) {
            const float* src = xin + (size_t)gn * (TILE * H);
            xn0 = __ldg(src + f0);
            xn1 = __ldg(src + f1);
        }

        if (act) {
            const u32 bT = xb + cur * (TILE * 68 * 4);
#pragma unroll
            for (int sb = 0; sb < 2; sb++) {
                ull a0 = pack2(bg, 0.f), a1 = a0, a2 = a0, a3 = a0;
                const u32 bA = bT + sb * (4 * 272);
#pragma unroll
                for (int q = 0; q < 16; q++) {
                    ull u0, u1;
                    lds128(u0, u1, bA + 0 * 272 + q * 16);
                    fma2(a0, wih[2 * q], u0); fma2(a0, wih[2 * q + 1], u1);
                    lds128(u0, u1, bA + 1 * 272 + q * 16);
                    fma2(a1, wih[2 * q], u0); fma2(a1, wih[2 * q + 1], u1);
                    lds128(u0, u1, bA + 2 * 272 + q * 16);
                    fma2(a2, wih[2 * q], u0); fma2(a2, wih[2 * q + 1], u1);
                    lds128(u0, u1, bA + 3 * 272 + q * 16);
                    fma2(a3, wih[2 * q], u0); fma2(a3, wih[2 * q + 1], u1);
                }
                fma2(a0, wih[32], lds64(bA + 0 * 272 + 256));
                fma2(a1, wih[32], lds64(bA + 1 * 272 + 256));
                fma2(a2, wih[32], lds64(bA + 2 * 272 + 256));
                fma2(a3, wih[32], lds64(bA + 3 * 272 + 256));

                float* op = g_pre + ((size_t)gi * TILE + sb * 4) * G4 + tid;
                float2 s;
                s = unpack2(a0); op[0]      = s.x + s.y;
                s = unpack2(a1); op[G4]     = s.x + s.y;
                s = unpack2(a2); op[2 * G4] = s.x + s.y;
                s = unpack2(a3); op[3 * G4] = s.x + s.y;
            }
        }
        if (act && gn < NTILES) {
            xs[cur ^ 1][s0] = xn0;
            xs[cur ^ 1][s1] = xn1;
        }
        __syncthreads();
        cur ^= 1;
    }
}

// ============================================================================
// Recurrent kernel: single barrier per step; lane-quad gate ownership.
// 256 CTAs x 2 rows, 288 threads, 2 CTAs/SM.
// warp w owns units 8w..8w+7 (w=8: unit 64, lanes 0-3); lane = unit*4 + k.
// ============================================================================
__global__ void __launch_bounds__(RTHR, 2)
recur_kernel(const float* __restrict__ w_hh, int write_all)
{
    __shared__ __align__(16) float h_sm[2][2 * 68];   // double-buffered, 2 rows

    const int tid  = threadIdx.x;
    const int b0   = blockIdx.x * 2;
    const int w    = tid >> 5;
    const int lane = tid & 31;
    int j = w * 8 + (lane >> 2);          // hidden unit
    const bool valid = (j < H);
    if (j > 64) j = 64;                   // clamp invalid lanes (harmless dup)
    const int k     = lane & 3;           // 0=i 1=f 2=g 3=o
    const int gidx  = k * 65 + j;         // gate row in W_hh / pre
    const int lbase = lane & ~3;

    ull whh[33];
    {
        const float* wh = w_hh + gidx * H;
#pragma unroll
        for (int q = 0; q < 32; q++)
            whh[q] = pack2(__ldg(wh + 2 * q), __ldg(wh + 2 * q + 1));
        whh[32] = pack2(__ldg(wh + 64), 0.f);
    }

    const float* p0 = g_pre + ((size_t)(b0 + 0) * T) * G4 + gidx;
    const float* p1 = g_pre + ((size_t)(b0 + 1) * T) * G4 + gidx;
    float* o0 = write_all ? g_h1 + ((size_t)(b0 + 0) * T) * H + j
                          : g_hN + (size_t)(b0 + 0) * H + j;
    float* o1 = write_all ? g_h1 + ((size_t)(b0 + 1) * T) * H + j
                          : g_hN + (size_t)(b0 + 1) * H + j;

    for (int q = tid; q < 2 * 2 * 68; q += RTHR) (&h_sm[0][0])[q] = 0.f;
    __syncthreads();

    const u32 hb = (u32)__cvta_generic_to_shared(&h_sm[0][0]);
    const bool is_t = (k == 2);

    float cA = 0.f, cB = 0.f;
    float pv0 = __ldg(p0), pv1 = __ldg(p1);

    int cur = 0;
    for (int t = 0; t < T; t++) {
        float pn0 = 0.f, pn1 = 0.f;
        if (t + 1 < T) {
            pn0 = __ldg(p0 + (size_t)(t + 1) * G4);
            pn1 = __ldg(p1 + (size_t)(t + 1) * G4);
        }

        // ---- matvec: raw gate = pre + h·W_hh (2 rows, 2 chains each) ----
        ull a00 = 0ull, a01 = 0ull, a10 = 0ull, a11 = 0ull;
        const u32 hA = hb + cur * (2 * 68 * 4);
        const u32 hB = hA + 272;
#pragma unroll
        for (int q = 0; q < 8; q++) {
            ull u0, u1, v0, v1;
            lds128(u0, u1, hA + q * 32);
            lds128(v0, v1, hB + q * 32);
            fma2(a00, whh[4 * q],     u0); fma2(a01, whh[4 * q + 1], u1);
            fma2(a10, whh[4 * q],     v0); fma2(a11, whh[4 * q + 1], v1);
            lds128(u0, u1, hA + q * 32 + 16);
            lds128(v0, v1, hB + q * 32 + 16);
            fma2(a00, whh[4 * q + 2], u0); fma2(a01, whh[4 * q + 3], u1);
            fma2(a10, whh[4 * q + 2], v0); fma2(a11, whh[4 * q + 3], v1);
        }
        fma2(a00, whh[32], lds64(hA + 256));
        fma2(a10, whh[32], lds64(hB + 256));

        float2 s0 = unpack2(a00), s1 = unpack2(a01);
        float2 s2 = unpack2(a10), s3 = unpack2(a11);
        float vA = ((s0.x + s0.y) + (s1.x + s1.y)) + pv0;
        float vB = ((s2.x + s2.y) + (s3.x + s3.y)) + pv1;

        // ---- activate OWN gate (i/f/o sigmoid, g tanh) ----
        float zA = is_t ? 2.f * vA : vA;
        float zB = is_t ? 2.f * vB : vB;
        float sA = __fdividef(1.f, 1.f + __expf(-zA));
        float sB = __fdividef(1.f, 1.f + __expf(-zB));
        float aA = is_t ? (2.f * sA - 1.f) : sA;
        float aB = is_t ? (2.f * sB - 1.f) : sB;

        // ---- quad gather via full-mask converged idx-shfls (8, independent) ----
        float iA = __shfl_sync(0xffffffffu, aA, lbase + 0);
        float fA = __shfl_sync(0xffffffffu, aA, lbase + 1);
        float gA = __shfl_sync(0xffffffffu, aA, lbase + 2);
        float oA = __shfl_sync(0xffffffffu, aA, lbase + 3);
        float iB = __shfl_sync(0xffffffffu, aB, lbase + 0);
        float fB = __shfl_sync(0xffffffffu, aB, lbase + 1);
        float gB = __shfl_sync(0xffffffffu, aB, lbase + 2);
        float oB = __shfl_sync(0xffffffffu, aB, lbase + 3);

        // ---- redundant cell update (bit-identical in all 4 quad lanes) ----
        cA = fA * cA + iA * gA;
        cB = fB * cB + iB * gB;
        float hAv = oA * fast_tanh(cA);
        float hBv = oB * fast_tanh(cB);

        // ---- lane k==0 publishes h ----
        float* nb = &h_sm[cur ^ 1][0];
        if (k == 0 && valid) {
            nb[j]      = hAv;
            nb[68 + j] = hBv;
            if (write_all) {
                o0[(size_t)t * H] = hAv;
                o1[(size_t)t * H] = hBv;
            } else if (t == T - 1) {
                o0[0] = hAv;
                o1[0] = hBv;
            }
        }
        pv0 = pn0; pv1 = pn1;
        __syncthreads();
        cur ^= 1;
    }
}

// ============================================================================
// out[b] = g_hN[b,:] . w_lin + b_lin
// ============================================================================
__global__ void final_linear_kernel(const float* __restrict__ w_lin,
                                    const float* __restrict__ b_lin,
                                    float* __restrict__ out)
{
    __shared__ float w[72];
    const int tid = threadIdx.x;
    if (tid < H) w[tid] = __ldg(w_lin + tid);
    __syncthreads();
    const int b = blockIdx.x * blockDim.x + tid;
    if (b < B) {
        const float* h = g_hN + (size_t)b * H;
        float s = __ldg(b_lin);
#pragma unroll
        for (int i = 0; i < H; i++) s += h[i] * w[i];
        out[b] = s;
    }
}

// ============================================================================
extern "C" void kernel_launch(void* const* d_in, const int* in_sizes, int n_in,
                              void* d_out, int out_size)
{
    const float* x     = (const float*)d_in[0];
    const float* w_ih0 = (const float*)d_in[1];
    const float* w_hh0 = (const float*)d_in[2];
    const float* b_ih0 = (const float*)d_in[3];
    const float* b_hh0 = (const float*)d_in[4];
    const float* w_ih1 = (const float*)d_in[5];
    const float* w_hh1 = (const float*)d_in[6];
    const float* b_ih1 = (const float*)d_in[7];
    const float* b_hh1 = (const float*)d_in[8];
    const float* w_lin = (const float*)d_in[9];
    const float* b_lin = (const float*)d_in[10];

    pre_kernel<<<PGRID, PTHR>>>(x, w_ih0, b_ih0, b_hh0, 0);
    recur_kernel<<<RGRID, RTHR>>>(w_hh0, 1);
    pre_kernel<<<PGRID, PTHR>>>(x, w_ih1, b_ih1, b_hh1, 1);
    recur_kernel<<<RGRID, RTHR>>>(w_hh1, 0);
    final_linear_kernel<<<2, 256>>>(w_lin, b_lin, (float*)d_out);
}